// round 8
// baseline (speedup 1.0000x reference)
#include <cuda_runtime.h>

#define MAXDISP 192
#define HH      192
#define WW      384
#define WD      (WW + MAXDISP - 1)   /* 575 */
#define HW      (HH * WW)            /* 73728 */

#define NCHUNK  8                    /* d-chunks */
#define DPC     (MAXDISP / NCHUNK)   /* 24 disparities per chunk */
#define T1      128                  /* kernel-1 threads */

// v layout: [1][4][D][H][WD]  ch 0 = logits, ch 1..3 = color
// out layout: color_1[3*HW] | color_2[3*HW] | disp_1[HW] | disp_2[HW]
// partials: part[chunk][h][view][val][w]  val: 0=l 1=a_d 2..4=a_c
__device__ float g_part[NCHUNK][HH][2][5][WW];   // 23.6 MB scratch

__global__ __launch_bounds__(T1, 8)
void vr_partial_kernel(const float* __restrict__ v) {
    const int tid   = threadIdx.x;
    const int h     = blockIdx.x % HH;
    const int chunk = blockIdx.x / HH;
    const int d0    = chunk * DPC;

    __shared__ float row[4][WD + 1];   // one (d,h) row, all 4 channels

    // 6 tasks per thread: k<3 -> view0 px = tid + k*128 ; k>=3 -> view1 same px
    float acc[6][5];
    #pragma unroll
    for (int k = 0; k < 6; ++k)
        #pragma unroll
        for (int t = 0; t < 5; ++t) acc[k][t] = 0.f;

    const int stride_d = HH * WD;            // 110400
    const int stride_c = MAXDISP * HH * WD;  // 21196800

    for (int i = 0; i < DPC; ++i) {
        const int d     = d0 + i;
        const int sh    = MAXDISP - 1 - d;         // view-2 column shift
        const int ncols = WD - d;                  // cols needed: [0, 575-d)
        const float dv  = (float)sh;

        // stream this (d,h) row: 4 channels x ncols floats, fully contiguous
        const float* __restrict__ rbase = v + d * stride_d + h * WD;
        #pragma unroll
        for (int ch = 0; ch < 4; ++ch) {
            const float* __restrict__ src = rbase + ch * stride_c;
            for (int col = tid; col < ncols; col += T1)
                row[ch][col] = src[col];
        }
        __syncthreads();

        // both views computed from the same staged row
        #pragma unroll
        for (int k = 0; k < 6; ++k) {
            const int px  = tid + (k % 3) * T1;    // 0..383
            const int col = (k < 3) ? px : (px + sh);

            const float b  = row[0][col];
            const float q0 = row[1][col];
            const float q1 = row[2][col];
            const float q2 = row[3][col];

            // no max-subtraction: logits ~ N(0,1); exp cannot overflow fp32 and
            // the softmax ratio is shift-invariant; partials are linear.
            const float e = __expf(b);

            acc[k][0] += e;
            acc[k][1]  = fmaf(e, dv, acc[k][1]);
            acc[k][2]  = fmaf(e, q0, acc[k][2]);
            acc[k][3]  = fmaf(e, q1, acc[k][3]);
            acc[k][4]  = fmaf(e, q2, acc[k][4]);
        }
        __syncthreads();   // before smem row is overwritten
    }

    // write partials: coalesced per (view,val)
    #pragma unroll
    for (int k = 0; k < 6; ++k) {
        const int view = (k < 3) ? 0 : 1;
        const int px   = tid + (k % 3) * T1;
        #pragma unroll
        for (int t = 0; t < 5; ++t)
            g_part[chunk][h][view][t][px] = acc[k][t];
    }
}

__global__ __launch_bounds__(256)
void vr_reduce_kernel(float* __restrict__ out) {
    const int pix = blockIdx.x * 256 + threadIdx.x;
    if (pix >= HW) return;
    const int h = pix / WW;
    const int w = pix % WW;

    float s[2][5];
    #pragma unroll
    for (int vw = 0; vw < 2; ++vw)
        #pragma unroll
        for (int t = 0; t < 5; ++t) s[vw][t] = 0.f;

    #pragma unroll
    for (int c = 0; c < NCHUNK; ++c)
        #pragma unroll
        for (int vw = 0; vw < 2; ++vw)
            #pragma unroll
            for (int t = 0; t < 5; ++t)
                s[vw][t] += g_part[c][h][vw][t][w];

    const float r1 = 1.0f / s[0][0];
    const float r2 = 1.0f / s[1][0];

    out[0 * HW + pix] = s[0][2] * r1;   // color_1
    out[1 * HW + pix] = s[0][3] * r1;
    out[2 * HW + pix] = s[0][4] * r1;
    out[3 * HW + pix] = s[1][2] * r2;   // color_2
    out[4 * HW + pix] = s[1][3] * r2;
    out[5 * HW + pix] = s[1][4] * r2;
    out[6 * HW + pix] = s[0][1] * r1;   // disp_1
    out[7 * HW + pix] = s[1][1] * r2;   // disp_2
}

extern "C" void kernel_launch(void* const* d_in, const int* in_sizes, int n_in,
                              void* d_out, int out_size) {
    const float* v = (const float*)d_in[0];
    float* out = (float*)d_out;

    vr_partial_kernel<<<NCHUNK * HH, T1>>>(v);            // 1536 blocks
    vr_reduce_kernel<<<(HW + 255) / 256, 256>>>(out);     // 288 blocks
}

// round 9
// speedup vs baseline: 2.9546x; 2.9546x over previous
#include <cuda_runtime.h>

#define MAXDISP 192
#define HH      192
#define WW      384
#define WD      (WW + MAXDISP - 1)   /* 575 */
#define HW      (HH * WW)            /* 73728 */

#define NCHUNK 4                     /* D-chunks per view (warps = view x chunk) */
#define DPC    (MAXDISP / NCHUNK)    /* 48 disparities per chunk */
#define PIX    32                    /* pixels per block */

// v layout: [1][4][D][H][WD]  ch 0 = logits, ch 1..3 = color
// out layout: color_1[3*HW] | color_2[3*HW] | disp_1[HW] | disp_2[HW]
// per-warp accumulators: 0:l  1:a_d  2..4:a_c

__global__ __launch_bounds__(256, 6)
void volume_render_v5_kernel(const float* __restrict__ v, float* __restrict__ out) {
    const int lane  = threadIdx.x & 31;
    const int warp  = threadIdx.x >> 5;
    const int view  = warp & 1;          // 0: col=w, 1: col=w+shift
    const int chunk = warp >> 1;         // 0..3

    const int pix0 = blockIdx.x * PIX;
    const int h    = pix0 / WW;
    const int w0   = pix0 % WW;

    const int stride_d = HH * WD;            // 110400
    const int stride_c = MAXDISP * HH * WD;  // 21196800

    const int d0  = chunk * DPC;
    const int sh0 = view ? (MAXDISP - 1 - d0) : 0;   // initial column shift
    // offset step per d: +stride_d for view1, +stride_d-1 for view2 (shift shrinks)
    const int step = stride_d - view;

    const float* __restrict__ p = v + d0 * stride_d + h * WD + w0 + lane + sh0;

    float l = 0.f, ad = 0.f, ac0 = 0.f, ac1 = 0.f, ac2 = 0.f;
    float dv = (float)(MAXDISP - 1 - d0);    // disparity value = D-1-d

    // unroll 8 -> up to 32 independent LDGs batched per warp (deep MLP);
    // launch_bounds(256,6) keeps regs <= 42 so >= 75% occupancy is guaranteed.
    #pragma unroll 8
    for (int i = 0; i < DPC; ++i) {
        // 4 independent coalesced loads
        const float b  = p[0];
        const float q0 = p[stride_c];
        const float q1 = p[2 * stride_c];
        const float q2 = p[3 * stride_c];

        // no max-subtraction: logits ~ N(0,1); exp cannot overflow fp32 and the
        // softmax ratio is shift-invariant; partials are linear -> splittable.
        const float e = __expf(b);

        l   += e;
        ad   = fmaf(e, dv, ad);
        ac0  = fmaf(e, q0, ac0);
        ac1  = fmaf(e, q1, ac1);
        ac2  = fmaf(e, q2, ac2);

        p  += step;
        dv -= 1.0f;
    }

    // warp index = chunk*2 + view ; 8 warps x 5 values x 32 px = 5 KB
    __shared__ float red[2 * NCHUNK][5][PIX];
    red[warp][0][lane] = l;
    red[warp][1][lane] = ad;
    red[warp][2][lane] = ac0;
    red[warp][3][lane] = ac1;
    red[warp][4][lane] = ac2;
    __syncthreads();

    // reduce over chunks: fin[view][val][px], 320 tasks over 256 threads
    __shared__ float fin[2][5][PIX];
    for (int t = threadIdx.x; t < 2 * 5 * PIX; t += 256) {
        const int vw  = t / (5 * PIX);
        const int val = (t / PIX) % 5;
        const int px  = t & 31;
        float s = 0.f;
        #pragma unroll
        for (int cc = 0; cc < NCHUNK; ++cc) s += red[cc * 2 + vw][val][px];
        fin[vw][val][px] = s;
    }
    __syncthreads();

    // 8 outputs x 32 px = 256 tasks, one per thread
    // outv 0-2: color_1 ; 3-5: color_2 ; 6: disp_1 ; 7: disp_2
    const int outv = threadIdx.x >> 5;
    const int px   = threadIdx.x & 31;
    const int vw   = (outv < 3) ? 0 : (outv < 6 ? 1 : (outv - 6));
    const int val  = (outv < 6) ? (2 + outv - vw * 3) : 1;

    const float a = fin[vw][val][px];
    const float s = fin[vw][0][px];
    out[outv * HW + pix0 + px] = a / s;
}

extern "C" void kernel_launch(void* const* d_in, const int* in_sizes, int n_in,
                              void* d_out, int out_size) {
    const float* v = (const float*)d_in[0];
    float* out = (float*)d_out;

    const int blocks = HW / PIX;   // 2304
    volume_render_v5_kernel<<<blocks, 256>>>(v, out);
}